// round 12
// baseline (speedup 1.0000x reference)
#include <cuda_runtime.h>
#include <stdint.h>

// Problem constants (shapes fixed by dataset; index/full read from device).
#define M_ROWS   100000
#define D_FEAT   1024
#define BATCH_N  4096
#define D_VEC    (D_FEAT / 4)                 // 256 float4 per row
#define TOT_VEC  ((long)M_ROWS * (long)D_VEC) // 25,600,000 float4 per array
#define ROWS_PER_CTA 4
#define COPY_BLOCKS  (M_ROWS / ROWS_PER_CTA)  // 25000, exact

// Output layout (floats):
//   [0, M*D)            new_feat
//   [M*D, 2*M*D)        new_pred
//   [2*M*D, 2*M*D + M)  new_conf
//   +M                  conf_mean
//   +M+1                utilization
#define OUT_CONF_OFF  (2L * M_ROWS * D_FEAT)

// ---------------------------------------------------------------------------
// Single fused kernel, 4 memory rows per CTA.
//   blocks [0, COPY_BLOCKS): block b handles rows [4b, 4b+4).
//     - 256 threads each copy one float4 column slot of all 4 rows, for both
//       feat and pred (8 independent 16B loads in flight per thread).
//     - thread 0 writes new_conf for the 4 rows (same predicates, free).
//   block COPY_BLOCKS: conf_mean (4096-elem reduction) + utilization.
// Plain ld/st (R5/R10 showed streaming hints cost ~3% HBM bandwidth).
// ---------------------------------------------------------------------------
__global__ void __launch_bounds__(256)
pm_fused(const float4* __restrict__ feat,
         const float4* __restrict__ pred,
         const float*  __restrict__ conf,
         const float4* __restrict__ mfeat,
         const float4* __restrict__ mpred,
         const float*  __restrict__ mconf,
         const int*    __restrict__ midx,
         const int*    __restrict__ mfull,
         float4*       __restrict__ out)        // base of output buffer
{
    int b = blockIdx.x;
    int t = threadIdx.x;

    if (b < COPY_BLOCKS) {
        int mi   = *midx;
        int row0 = b * ROWS_PER_CTA;
        float*  out_conf = (float*)out + OUT_CONF_OFF;

        #pragma unroll
        for (int k = 0; k < ROWS_PER_CTA; k++) {
            int row = row0 + k;
            int r   = row - mi;
            if (r < 0) r += M_ROWS;

            long j = ((long)row << 8) + t;      // row-major float4 index

            if (r < BATCH_N) {
                long src = ((long)r << 8) + t;
                out[j]           = feat[src];
                out[TOT_VEC + j] = pred[src];
                if (t == 0) out_conf[row] = conf[r];
            } else {
                out[j]           = mfeat[j];
                out[TOT_VEC + j] = mpred[j];
                if (t == 0) out_conf[row] = mconf[row];
            }
        }
        return;
    }

    // ---- scalar block: conf_mean + utilization ----
    __shared__ float red[8];

    float s = 0.0f;
    #pragma unroll
    for (int i = 0; i < BATCH_N; i += 256)      // 16 values per thread
        s += conf[i + t];

    #pragma unroll
    for (int o = 16; o > 0; o >>= 1)
        s += __shfl_xor_sync(0xFFFFFFFFu, s, o);

    if ((t & 31) == 0) red[t >> 5] = s;
    __syncthreads();

    if (t < 32) {
        float v = (t < 8) ? red[t] : 0.0f;
        #pragma unroll
        for (int o = 4; o > 0; o >>= 1)
            v += __shfl_xor_sync(0xFFFFFFFFu, v, o);
        if (t == 0) {
            float* out_f = (float*)out;
            out_f[OUT_CONF_OFF + M_ROWS] = v / (float)BATCH_N;

            int  mi        = *midx;
            int  new_index = (mi + BATCH_N) % M_ROWS;
            bool wrapped   = (mi + BATCH_N) >= M_ROWS;
            bool full      = (*mfull != 0) || wrapped;
            out_f[OUT_CONF_OFF + M_ROWS + 1] =
                full ? 1.0f : (float)new_index / (float)M_ROWS;
        }
    }
}

// ---------------------------------------------------------------------------
extern "C" void kernel_launch(void* const* d_in, const int* in_sizes, int n_in,
                              void* d_out, int out_size)
{
    const float* features     = (const float*)d_in[0];
    const float* predictions  = (const float*)d_in[1];
    const float* confidences  = (const float*)d_in[2];
    const float* mem_feat     = (const float*)d_in[3];
    const float* mem_pred     = (const float*)d_in[4];
    const float* mem_conf     = (const float*)d_in[5];
    const int*   mem_index    = (const int*)d_in[6];
    const int*   mem_full     = (const int*)d_in[7];

    pm_fused<<<COPY_BLOCKS + 1, 256>>>(
        (const float4*)features, (const float4*)predictions, confidences,
        (const float4*)mem_feat, (const float4*)mem_pred, mem_conf,
        mem_index, mem_full, (float4*)d_out);
}

// round 13
// speedup vs baseline: 1.0177x; 1.0177x over previous
#include <cuda_runtime.h>
#include <stdint.h>

// Problem constants (shapes fixed by dataset; index/full read from device).
#define M_ROWS   100000
#define D_FEAT   1024
#define BATCH_N  4096
#define D_VEC    (D_FEAT / 4)                 // 256 float4 per row
#define TOT_VEC  ((long)M_ROWS * (long)D_VEC) // 25,600,000 float4 per array

// Output layout (floats):
//   [0, M*D)            new_feat
//   [M*D, 2*M*D)        new_pred
//   [2*M*D, 2*M*D + M)  new_conf
//   +M                  conf_mean
//   +M+1                utilization
#define OUT_CONF_OFF  (2L * M_ROWS * D_FEAT)

// ---------------------------------------------------------------------------
// Single fused kernel — best measured configuration (R10):
//   1 memory row per CTA, plain loads/stores (no cache hints).
//   Measured: 229.9us kernel, DRAM 87.2%, 6.91 TB/s.
//   R12 showed 4 rows/CTA regresses (MLP batching -> cross-CTA L1tex
//   contention, DRAM 84.9%); R5 showed __ldcs/__stcs regress (DRAM 84.8%).
//
//   blocks [0, M_ROWS): block b = memory row b.
//     - 256 threads copy the 256 float4 slots of feat and pred for that row,
//       source selected by the circular-buffer predicate.
//     - thread 0 additionally writes new_conf[b] (same predicate, free).
//   block M_ROWS: computes conf_mean (4096-elem reduction) + utilization.
// ---------------------------------------------------------------------------
__global__ void __launch_bounds__(256)
pm_fused(const float4* __restrict__ feat,
         const float4* __restrict__ pred,
         const float*  __restrict__ conf,
         const float4* __restrict__ mfeat,
         const float4* __restrict__ mpred,
         const float*  __restrict__ mconf,
         const int*    __restrict__ midx,
         const int*    __restrict__ mfull,
         float4*       __restrict__ out)        // base of output buffer
{
    int b = blockIdx.x;
    int t = threadIdx.x;

    if (b < M_ROWS) {
        // ---- bulk circular-buffer copy ----
        int mi = *midx;
        int r  = b - mi;
        if (r < 0) r += M_ROWS;

        long j = ((long)b << 8) + t;            // row-major float4 index
        float4* out_feat = out;
        float4* out_pred = out + TOT_VEC;
        float*  out_conf = (float*)out + OUT_CONF_OFF;

        if (r < BATCH_N) {
            long src = ((long)r << 8) + t;
            out_feat[j] = feat[src];
            out_pred[j] = pred[src];
            if (t == 0) out_conf[b] = conf[r];
        } else {
            out_feat[j] = mfeat[j];
            out_pred[j] = mpred[j];
            if (t == 0) out_conf[b] = mconf[b];
        }
        return;
    }

    // ---- scalar block: conf_mean + utilization ----
    __shared__ float red[8];

    float s = 0.0f;
    #pragma unroll
    for (int i = 0; i < BATCH_N; i += 256)      // 16 values per thread
        s += conf[i + t];

    #pragma unroll
    for (int o = 16; o > 0; o >>= 1)
        s += __shfl_xor_sync(0xFFFFFFFFu, s, o);

    if ((t & 31) == 0) red[t >> 5] = s;
    __syncthreads();

    if (t < 32) {
        float v = (t < 8) ? red[t] : 0.0f;
        #pragma unroll
        for (int o = 4; o > 0; o >>= 1)
            v += __shfl_xor_sync(0xFFFFFFFFu, v, o);
        if (t == 0) {
            float* out_f = (float*)out;
            out_f[OUT_CONF_OFF + M_ROWS] = v / (float)BATCH_N;

            int  mi        = *midx;
            int  new_index = (mi + BATCH_N) % M_ROWS;
            bool wrapped   = (mi + BATCH_N) >= M_ROWS;
            bool full      = (*mfull != 0) || wrapped;
            out_f[OUT_CONF_OFF + M_ROWS + 1] =
                full ? 1.0f : (float)new_index / (float)M_ROWS;
        }
    }
}

// ---------------------------------------------------------------------------
extern "C" void kernel_launch(void* const* d_in, const int* in_sizes, int n_in,
                              void* d_out, int out_size)
{
    const float* features     = (const float*)d_in[0];
    const float* predictions  = (const float*)d_in[1];
    const float* confidences  = (const float*)d_in[2];
    const float* mem_feat     = (const float*)d_in[3];
    const float* mem_pred     = (const float*)d_in[4];
    const float* mem_conf     = (const float*)d_in[5];
    const int*   mem_index    = (const int*)d_in[6];
    const int*   mem_full     = (const int*)d_in[7];

    pm_fused<<<M_ROWS + 1, 256>>>(
        (const float4*)features, (const float4*)predictions, confidences,
        (const float4*)mem_feat, (const float4*)mem_pred, mem_conf,
        mem_index, mem_full, (float4*)d_out);
}

// round 15
// speedup vs baseline: 1.0262x; 1.0084x over previous
#include <cuda_runtime.h>
#include <stdint.h>

// Problem constants (shapes fixed by dataset; index/full read from device).
#define M_ROWS   100000
#define D_FEAT   1024
#define BATCH_N  4096
#define D_VEC    (D_FEAT / 4)                 // 256 float4 per row
#define TOT_VEC  ((long)M_ROWS * (long)D_VEC) // 25,600,000 float4 per array
#define TPB          1024
#define ROWS_PER_CTA 4                        // 1024 threads = 4 rows x 256 slots
#define COPY_BLOCKS  (M_ROWS / ROWS_PER_CTA)  // 25000, exact

// Output layout (floats):
//   [0, M*D)            new_feat
//   [M*D, 2*M*D)        new_pred
//   [2*M*D, 2*M*D + M)  new_conf
//   +M                  conf_mean
//   +M+1                utilization
#define OUT_CONF_OFF  (2L * M_ROWS * D_FEAT)

// ---------------------------------------------------------------------------
// Single fused kernel, 1024 threads/CTA, 4 rows/CTA, ONE (row,slot) pair per
// thread — per-thread MLP stays 2 (the measured optimum from R10/R13; the R12
// regression came from MLP=8 per thread, not row batching itself).
//   blocks [0, COPY_BLOCKS): block b handles rows [4b, 4b+4).
//     thread t: row = 4b + (t>>8), slot = t&255. Copies feat+pred slot;
//     slot==0 threads also write new_conf[row] (same predicate, free).
//   block COPY_BLOCKS: conf_mean (4096-elem reduction) + utilization.
// Plain ld/st (streaming hints measured -3% HBM bandwidth in R5/R10).
// ---------------------------------------------------------------------------
__global__ void __launch_bounds__(TPB)
pm_fused(const float4* __restrict__ feat,
         const float4* __restrict__ pred,
         const float*  __restrict__ conf,
         const float4* __restrict__ mfeat,
         const float4* __restrict__ mpred,
         const float*  __restrict__ mconf,
         const int*    __restrict__ midx,
         const int*    __restrict__ mfull,
         float4*       __restrict__ out)        // base of output buffer
{
    int b = blockIdx.x;
    int t = threadIdx.x;

    if (b < COPY_BLOCKS) {
        // ---- bulk circular-buffer copy ----
        int mi   = *midx;
        int row  = b * ROWS_PER_CTA + (t >> 8); // 4 rows per block
        int slot = t & 255;

        int r = row - mi;
        if (r < 0) r += M_ROWS;

        long j = ((long)row << 8) + slot;       // row-major float4 index
        float4* out_feat = out;
        float4* out_pred = out + TOT_VEC;
        float*  out_conf = (float*)out + OUT_CONF_OFF;

        if (r < BATCH_N) {
            long src = ((long)r << 8) + slot;
            out_feat[j] = feat[src];
            out_pred[j] = pred[src];
            if (slot == 0) out_conf[row] = conf[r];
        } else {
            out_feat[j] = mfeat[j];
            out_pred[j] = mpred[j];
            if (slot == 0) out_conf[row] = mconf[row];
        }
        return;
    }

    // ---- scalar block: conf_mean + utilization (1024 threads) ----
    __shared__ float red[32];

    float s = 0.0f;
    #pragma unroll
    for (int i = 0; i < BATCH_N; i += TPB)      // 4 values per thread
        s += conf[i + t];

    #pragma unroll
    for (int o = 16; o > 0; o >>= 1)
        s += __shfl_xor_sync(0xFFFFFFFFu, s, o);

    if ((t & 31) == 0) red[t >> 5] = s;
    __syncthreads();

    if (t < 32) {
        float v = red[t];                       // 1024/32 = 32 partials
        #pragma unroll
        for (int o = 16; o > 0; o >>= 1)
            v += __shfl_xor_sync(0xFFFFFFFFu, v, o);
        if (t == 0) {
            float* out_f = (float*)out;
            out_f[OUT_CONF_OFF + M_ROWS] = v / (float)BATCH_N;

            int  mi        = *midx;
            int  new_index = (mi + BATCH_N) % M_ROWS;
            bool wrapped   = (mi + BATCH_N) >= M_ROWS;
            bool full      = (*mfull != 0) || wrapped;
            out_f[OUT_CONF_OFF + M_ROWS + 1] =
                full ? 1.0f : (float)new_index / (float)M_ROWS;
        }
    }
}

// ---------------------------------------------------------------------------
extern "C" void kernel_launch(void* const* d_in, const int* in_sizes, int n_in,
                              void* d_out, int out_size)
{
    const float* features     = (const float*)d_in[0];
    const float* predictions  = (const float*)d_in[1];
    const float* confidences  = (const float*)d_in[2];
    const float* mem_feat     = (const float*)d_in[3];
    const float* mem_pred     = (const float*)d_in[4];
    const float* mem_conf     = (const float*)d_in[5];
    const int*   mem_index    = (const int*)d_in[6];
    const int*   mem_full     = (const int*)d_in[7];

    pm_fused<<<COPY_BLOCKS + 1, TPB>>>(
        (const float4*)features, (const float4*)predictions, confidences,
        (const float4*)mem_feat, (const float4*)mem_pred, mem_conf,
        mem_index, mem_full, (float4*)d_out);
}